// round 10
// baseline (speedup 1.0000x reference)
#include <cuda_runtime.h>
#include <cuda_bf16.h>
#include <cstdint>

// x [2,4096,4096] f32, weight [4096,4096] f32, bias [4096] f32 -> out f32
// M=8192, K=4096, N=4096

#define MAX_M 8192
#define MAX_K 4096
#define MAX_N 4096

__device__ int8_t g_xi8[(size_t)MAX_M * MAX_K];
__device__ int8_t g_wi8[(size_t)MAX_N * MAX_K];
__device__ float  g_xs[MAX_M];
__device__ float  g_ws[MAX_N];

// ---------------------------------------------------------------------------
// Fused per-row symmetric int8 quantization (weight rows then x rows).
// Single global read pass: row staged in shared memory.
// ---------------------------------------------------------------------------
__global__ void quant_fused_kernel(const float* __restrict__ w,
                                   const float* __restrict__ x,
                                   int8_t* __restrict__ wi8,
                                   int8_t* __restrict__ xi8,
                                   float* __restrict__ wsc,
                                   float* __restrict__ xsc,
                                   int K, int N) {
    extern __shared__ float4 buf[];  // K floats = K/4 float4 (16KB for K=4096)
    const int b = blockIdx.x;
    const float* src;
    int8_t* dst;
    float* sc;
    int row;
    if (b < N) { src = w; dst = wi8; sc = wsc; row = b; }
    else       { src = x; dst = xi8; sc = xsc; row = b - N; }

    const int nk4 = K >> 2;
    const float4* s4 = reinterpret_cast<const float4*>(src) + (size_t)row * nk4;
    char4* d4 = reinterpret_cast<char4*>(dst) + (size_t)row * nk4;

    float amax = 0.f;
    for (int i = threadIdx.x; i < nk4; i += blockDim.x) {
        float4 v = s4[i];
        buf[i] = v;
        amax = fmaxf(amax, fmaxf(fmaxf(fabsf(v.x), fabsf(v.y)),
                                 fmaxf(fabsf(v.z), fabsf(v.w))));
    }
    __shared__ float red[32];
    #pragma unroll
    for (int o = 16; o; o >>= 1) amax = fmaxf(amax, __shfl_xor_sync(0xffffffffu, amax, o));
    if ((threadIdx.x & 31) == 0) red[threadIdx.x >> 5] = amax;
    __syncthreads();
    if (threadIdx.x < 32) {
        float v = (threadIdx.x < (blockDim.x >> 5)) ? red[threadIdx.x] : 0.f;
        #pragma unroll
        for (int o = 16; o; o >>= 1) v = fmaxf(v, __shfl_xor_sync(0xffffffffu, v, o));
        if (threadIdx.x == 0) red[0] = fmaxf(v / 127.0f, 1e-12f);
    }
    __syncthreads();
    const float scale = red[0];
    if (threadIdx.x == 0) sc[row] = scale;

    for (int i = threadIdx.x; i < nk4; i += blockDim.x) {
        float4 v = buf[i];
        char4 q;
        q.x = (signed char)(int)fminf(fmaxf(rintf(v.x / scale), -128.f), 127.f);
        q.y = (signed char)(int)fminf(fmaxf(rintf(v.y / scale), -128.f), 127.f);
        q.z = (signed char)(int)fminf(fmaxf(rintf(v.z / scale), -128.f), 127.f);
        q.w = (signed char)(int)fminf(fmaxf(rintf(v.w / scale), -128.f), 127.f);
        d4[i] = q;
    }
}

// ---------------------------------------------------------------------------
// int8 GEMM: mma.sync.m16n8k32 + cp.async 5-stage pipeline + ldmatrix.
// Block 128x128, BK=64, 16 warps (4x4), warp tile 32x32, 512 threads.
// ---------------------------------------------------------------------------
#define BM 128
#define BN 128
#define BK 64
#define STAGES 5
#define ASTRIDE 80                       // 64B data + 16B pad: conflict-free
#define STAGE_BYTES (2 * BM * ASTRIDE)   // 20480
#define SMEM_BYTES (STAGES * STAGE_BYTES)

__device__ __forceinline__ uint32_t smem_u32(const void* p) {
    uint32_t a;
    asm("{ .reg .u64 t; cvta.to.shared.u64 t, %1; cvt.u32.u64 %0, t; }" : "=r"(a) : "l"(p));
    return a;
}
__device__ __forceinline__ void cp_async16(uint32_t dst, const void* src) {
    asm volatile("cp.async.cg.shared.global [%0], [%1], 16;" :: "r"(dst), "l"(src));
}
__device__ __forceinline__ void cp_commit() {
    asm volatile("cp.async.commit_group;" ::: "memory");
}
template <int W>
__device__ __forceinline__ void cp_wait() {
    asm volatile("cp.async.wait_group %0;" :: "n"(W) : "memory");
}
__device__ __forceinline__ void ldsm_x4(int& r0, int& r1, int& r2, int& r3, uint32_t a) {
    asm volatile("ldmatrix.sync.aligned.m8n8.x4.shared.b16 {%0,%1,%2,%3}, [%4];"
                 : "=r"(r0), "=r"(r1), "=r"(r2), "=r"(r3) : "r"(a));
}

__device__ __forceinline__ float finish_elem(int acc, float sx, float sw, float bias_bf) {
    float v = ((float)acc * sx) * sw;
    float o = __bfloat162float(__float2bfloat16(v));
    return __bfloat162float(__float2bfloat16(o + bias_bf));
}

__global__ void __launch_bounds__(512, 1) gemm_i8_kernel(
    const float* __restrict__ bias, float* __restrict__ out,
    int M, int N, int K) {
    extern __shared__ char smem[];
    const uint32_t sb = smem_u32(smem);

    const int tid = threadIdx.x;
    const int warp = tid >> 5, lane = tid & 31;
    const int m0 = blockIdx.y * BM;
    const int n0 = blockIdx.x * BN;
    const int wm = (warp >> 2) * 32;   // 4 warps in M
    const int wn = (warp & 3) * 32;    // 4 warps in N
    const int g = lane >> 2, tig = lane & 3;

    const int8_t* Ag = g_xi8 + (size_t)m0 * K;
    const int8_t* Bg = g_wi8 + (size_t)n0 * K;

    // cp.async: 512 16B segments per tile; 1 A-seg + 1 B-seg per thread.
    const int r_ld = tid >> 2, c_ld = (tid & 3) * 16;

    // ldmatrix lane offsets (byte offsets inside a stage tile)
    uint32_t aoff[2], boff[2];
    #pragma unroll
    for (int i = 0; i < 2; i++)
        aoff[i] = (uint32_t)((wm + i * 16 + (lane & 15)) * ASTRIDE + ((lane >> 4) << 4));
    #pragma unroll
    for (int jj = 0; jj < 2; jj++)
        boff[jj] = (uint32_t)((wn + ((jj << 1) + ((lane >> 4) & 1)) * 8 + (lane & 7)) * ASTRIDE
                              + (((lane >> 3) & 1) << 4));

    int acc[2][4][4];
    #pragma unroll
    for (int i = 0; i < 2; i++)
        #pragma unroll
        for (int j = 0; j < 4; j++)
            #pragma unroll
            for (int r = 0; r < 4; r++) acc[i][j][r] = 0;

    const int nchunks = K / BK;

    auto issue_stage = [&](int c) {
        const int s = c % STAGES;
        const int kt = c * BK;
        const uint32_t ab = sb + s * STAGE_BYTES;
        const uint32_t bb = ab + BM * ASTRIDE;
        cp_async16(ab + r_ld * ASTRIDE + c_ld, Ag + (size_t)r_ld * K + kt + c_ld);
        cp_async16(bb + r_ld * ASTRIDE + c_ld, Bg + (size_t)r_ld * K + kt + c_ld);
        cp_commit();
    };

    #pragma unroll
    for (int c = 0; c < STAGES - 1; c++) issue_stage(c);

    for (int c = 0; c < nchunks; c++) {
        cp_wait<STAGES - 2>();
        __syncthreads();

        // Exactly one commit per iteration keeps wait_group counting sound.
        if (c + STAGES - 1 < nchunks) issue_stage(c + STAGES - 1);
        else cp_commit();

        const int s = c % STAGES;
        const uint32_t ab = sb + s * STAGE_BYTES;
        const uint32_t bb = ab + BM * ASTRIDE;

        #pragma unroll
        for (int ks = 0; ks < BK; ks += 32) {
            int fa[2][4], fb[4][2];
            #pragma unroll
            for (int i = 0; i < 2; i++)
                ldsm_x4(fa[i][0], fa[i][1], fa[i][2], fa[i][3], ab + aoff[i] + ks);
            #pragma unroll
            for (int jj = 0; jj < 2; jj++)
                ldsm_x4(fb[2 * jj][0], fb[2 * jj][1], fb[2 * jj + 1][0], fb[2 * jj + 1][1],
                        bb + boff[jj] + ks);
            #pragma unroll
            for (int i = 0; i < 2; i++) {
                #pragma unroll
                for (int j = 0; j < 4; j++) {
                    asm volatile(
                        "mma.sync.aligned.m16n8k32.row.col.s32.s8.s8.s32 "
                        "{%0,%1,%2,%3},{%4,%5,%6,%7},{%8,%9},{%0,%1,%2,%3};"
                        : "+r"(acc[i][j][0]), "+r"(acc[i][j][1]),
                          "+r"(acc[i][j][2]), "+r"(acc[i][j][3])
                        : "r"(fa[i][0]), "r"(fa[i][1]), "r"(fa[i][2]), "r"(fa[i][3]),
                          "r"(fb[j][0]), "r"(fb[j][1]));
                }
            }
        }
        // No trailing barrier: next iteration's wait+sync protects stage reuse.
    }

    // Epilogue: dequant + bf16 round + bf16 bias add -> f32
    #pragma unroll
    for (int i = 0; i < 2; i++) {
        int r0 = m0 + wm + i * 16 + g;
        float sx0 = g_xs[r0];
        float sx1 = g_xs[r0 + 8];
        #pragma unroll
        for (int j = 0; j < 4; j++) {
            int c0 = n0 + wn + j * 8 + 2 * tig;
            float sw0 = g_ws[c0], sw1 = g_ws[c0 + 1];
            float bb0 = __bfloat162float(__float2bfloat16(bias[c0]));
            float bb1 = __bfloat162float(__float2bfloat16(bias[c0 + 1]));
            float2 o0, o1;
            o0.x = finish_elem(acc[i][j][0], sx0, sw0, bb0);
            o0.y = finish_elem(acc[i][j][1], sx0, sw1, bb1);
            o1.x = finish_elem(acc[i][j][2], sx1, sw0, bb0);
            o1.y = finish_elem(acc[i][j][3], sx1, sw1, bb1);
            *reinterpret_cast<float2*>(out + (size_t)r0 * N + c0) = o0;
            *reinterpret_cast<float2*>(out + (size_t)(r0 + 8) * N + c0) = o1;
        }
    }
}

// ---------------------------------------------------------------------------
extern "C" void kernel_launch(void* const* d_in, const int* in_sizes, int n_in,
                              void* d_out, int out_size) {
    const float* x      = (const float*)d_in[0];
    const float* weight = (const float*)d_in[1];
    const float* bias   = (const float*)d_in[2];
    float* out = (float*)d_out;

    const int N = in_sizes[2];
    const int K = in_sizes[1] / N;
    const int M = in_sizes[0] / K;

    int8_t* wi8; cudaGetSymbolAddress((void**)&wi8, g_wi8);
    int8_t* xi8; cudaGetSymbolAddress((void**)&xi8, g_xi8);
    float* ws;   cudaGetSymbolAddress((void**)&ws, g_ws);
    float* xs;   cudaGetSymbolAddress((void**)&xs, g_xs);

    quant_fused_kernel<<<N + M, 256, K * sizeof(float)>>>(weight, x, wi8, xi8, ws, xs, K, N);

    cudaFuncSetAttribute(gemm_i8_kernel, cudaFuncAttributeMaxDynamicSharedMemorySize, SMEM_BYTES);
    dim3 grid(N / BN, M / BM);
    gemm_i8_kernel<<<grid, 512, SMEM_BYTES>>>(bias, out, M, N, K);
}

// round 11
// speedup vs baseline: 1.8746x; 1.8746x over previous
#include <cuda_runtime.h>
#include <cuda_bf16.h>
#include <cstdint>

// x [2,4096,4096] f32, weight [4096,4096] f32, bias [4096] f32 -> out f32
// M=8192, K=4096, N=4096
// Quantized operands stored as bf16 (exact for ints in [-128,127]) so the
// GEMM can use mma.sync.m16n8k16.bf16 (fp32 acc) instead of the
// heavily-deprioritized legacy int8 IMMA path on sm_103a.

#define MAX_M 8192
#define MAX_K 4096
#define MAX_N 4096

__device__ __nv_bfloat16 g_xbf[(size_t)MAX_M * MAX_K];
__device__ __nv_bfloat16 g_wbf[(size_t)MAX_N * MAX_K];
__device__ float g_xs[MAX_M];
__device__ float g_ws[MAX_N];

// ---------------------------------------------------------------------------
// Fused per-row symmetric int8 quantization -> bf16-carried int values.
// ---------------------------------------------------------------------------
__global__ void quant_fused_kernel(const float* __restrict__ w,
                                   const float* __restrict__ x,
                                   __nv_bfloat16* __restrict__ wbf,
                                   __nv_bfloat16* __restrict__ xbf,
                                   float* __restrict__ wsc,
                                   float* __restrict__ xsc,
                                   int K, int N) {
    extern __shared__ float4 buf[];  // K floats
    const int b = blockIdx.x;
    const float* src;
    __nv_bfloat16* dst;
    float* sc;
    int row;
    if (b < N) { src = w; dst = wbf; sc = wsc; row = b; }
    else       { src = x; dst = xbf; sc = xsc; row = b - N; }

    const int nk4 = K >> 2;
    const float4* s4 = reinterpret_cast<const float4*>(src) + (size_t)row * nk4;
    __nv_bfloat162* d2 = reinterpret_cast<__nv_bfloat162*>(dst) + (size_t)row * (K >> 1);

    float amax = 0.f;
    for (int i = threadIdx.x; i < nk4; i += blockDim.x) {
        float4 v = s4[i];
        buf[i] = v;
        amax = fmaxf(amax, fmaxf(fmaxf(fabsf(v.x), fabsf(v.y)),
                                 fmaxf(fabsf(v.z), fabsf(v.w))));
    }
    __shared__ float red[32];
    #pragma unroll
    for (int o = 16; o; o >>= 1) amax = fmaxf(amax, __shfl_xor_sync(0xffffffffu, amax, o));
    if ((threadIdx.x & 31) == 0) red[threadIdx.x >> 5] = amax;
    __syncthreads();
    if (threadIdx.x < 32) {
        float v = (threadIdx.x < (blockDim.x >> 5)) ? red[threadIdx.x] : 0.f;
        #pragma unroll
        for (int o = 16; o; o >>= 1) v = fmaxf(v, __shfl_xor_sync(0xffffffffu, v, o));
        if (threadIdx.x == 0) red[0] = fmaxf(v / 127.0f, 1e-12f);
    }
    __syncthreads();
    const float scale = red[0];
    if (threadIdx.x == 0) sc[row] = scale;

    for (int i = threadIdx.x; i < nk4; i += blockDim.x) {
        float4 v = buf[i];
        float q0 = fminf(fmaxf(rintf(v.x / scale), -128.f), 127.f);
        float q1 = fminf(fmaxf(rintf(v.y / scale), -128.f), 127.f);
        float q2 = fminf(fmaxf(rintf(v.z / scale), -128.f), 127.f);
        float q3 = fminf(fmaxf(rintf(v.w / scale), -128.f), 127.f);
        __nv_bfloat162 p0, p1;
        p0.x = __float2bfloat16(q0); p0.y = __float2bfloat16(q1);
        p1.x = __float2bfloat16(q2); p1.y = __float2bfloat16(q3);
        d2[i * 2]     = p0;
        d2[i * 2 + 1] = p1;
    }
}

// ---------------------------------------------------------------------------
// bf16 GEMM: mma.sync.m16n8k16.bf16 + cp.async 5-stage pipeline + ldmatrix.
// Block 128x128, 64B k-slab per stage row (k=32 elems), 16 warps, warp 32x32.
// Byte layout identical to the previous int8 kernel.
// ---------------------------------------------------------------------------
#define BM 128
#define BN 128
#define BKB 64                           // bytes of K per stage row
#define STAGES 5
#define ASTRIDE 80                       // 64B data + 16B pad: conflict-free
#define STAGE_BYTES (2 * BM * ASTRIDE)   // 20480
#define SMEM_BYTES (STAGES * STAGE_BYTES)

__device__ __forceinline__ uint32_t smem_u32(const void* p) {
    uint32_t a;
    asm("{ .reg .u64 t; cvta.to.shared.u64 t, %1; cvt.u32.u64 %0, t; }" : "=r"(a) : "l"(p));
    return a;
}
__device__ __forceinline__ void cp_async16(uint32_t dst, const void* src) {
    asm volatile("cp.async.cg.shared.global [%0], [%1], 16;" :: "r"(dst), "l"(src));
}
__device__ __forceinline__ void cp_commit() {
    asm volatile("cp.async.commit_group;" ::: "memory");
}
template <int W>
__device__ __forceinline__ void cp_wait() {
    asm volatile("cp.async.wait_group %0;" :: "n"(W) : "memory");
}
__device__ __forceinline__ void ldsm_x4(int& r0, int& r1, int& r2, int& r3, uint32_t a) {
    asm volatile("ldmatrix.sync.aligned.m8n8.x4.shared.b16 {%0,%1,%2,%3}, [%4];"
                 : "=r"(r0), "=r"(r1), "=r"(r2), "=r"(r3) : "r"(a));
}

__device__ __forceinline__ float finish_elem(float accf, float sx, float sw, float bias_bf) {
    float v = (rintf(accf) * sx) * sw;                 // acc is integer-valued
    float o = __bfloat162float(__float2bfloat16(v));   // .astype(bf16)
    return __bfloat162float(__float2bfloat16(o + bias_bf));
}

__global__ void __launch_bounds__(512, 1) gemm_bf16_kernel(
    const float* __restrict__ bias, float* __restrict__ out,
    int M, int N, int K) {
    extern __shared__ char smem[];
    const uint32_t sb = smem_u32(smem);

    const int tid = threadIdx.x;
    const int warp = tid >> 5, lane = tid & 31;
    const int m0 = blockIdx.y * BM;
    const int n0 = blockIdx.x * BN;
    const int wm = (warp >> 2) * 32;   // 4 warps in M
    const int wn = (warp & 3) * 32;    // 4 warps in N
    const int g = lane >> 2, tig = lane & 3;

    const int Kb = K * 2;              // row length in bytes
    const int8_t* Ag = reinterpret_cast<const int8_t*>(g_xbf) + (size_t)m0 * Kb;
    const int8_t* Bg = reinterpret_cast<const int8_t*>(g_wbf) + (size_t)n0 * Kb;

    // cp.async: 512 16B segments per tile; 1 A-seg + 1 B-seg per thread.
    const int r_ld = tid >> 2, c_ld = (tid & 3) * 16;

    // ldmatrix lane offsets (byte offsets inside a stage tile)
    uint32_t aoff[2], boff[2];
    #pragma unroll
    for (int i = 0; i < 2; i++)
        aoff[i] = (uint32_t)((wm + i * 16 + (lane & 15)) * ASTRIDE + ((lane >> 4) << 4));
    #pragma unroll
    for (int jj = 0; jj < 2; jj++)
        boff[jj] = (uint32_t)((wn + ((jj << 1) + ((lane >> 4) & 1)) * 8 + (lane & 7)) * ASTRIDE
                              + (((lane >> 3) & 1) << 4));

    float acc[2][4][4];
    #pragma unroll
    for (int i = 0; i < 2; i++)
        #pragma unroll
        for (int j = 0; j < 4; j++)
            #pragma unroll
            for (int r = 0; r < 4; r++) acc[i][j][r] = 0.f;

    const int nchunks = Kb / BKB;      // 128

    auto issue_stage = [&](int c) {
        const int s = c % STAGES;
        const int kt = c * BKB;
        const uint32_t ab = sb + s * STAGE_BYTES;
        const uint32_t bb = ab + BM * ASTRIDE;
        cp_async16(ab + r_ld * ASTRIDE + c_ld, Ag + (size_t)r_ld * Kb + kt + c_ld);
        cp_async16(bb + r_ld * ASTRIDE + c_ld, Bg + (size_t)r_ld * Kb + kt + c_ld);
        cp_commit();
    };

    #pragma unroll
    for (int c = 0; c < STAGES - 1; c++) issue_stage(c);

    for (int c = 0; c < nchunks; c++) {
        cp_wait<STAGES - 2>();
        __syncthreads();

        if (c + STAGES - 1 < nchunks) issue_stage(c + STAGES - 1);
        else cp_commit();   // exactly one commit per iteration

        const int s = c % STAGES;
        const uint32_t ab = sb + s * STAGE_BYTES;
        const uint32_t bb = ab + BM * ASTRIDE;

        #pragma unroll
        for (int ks = 0; ks < BKB; ks += 32) {   // 32B = k16 of bf16
            int fa[2][4], fb[4][2];
            #pragma unroll
            for (int i = 0; i < 2; i++)
                ldsm_x4(fa[i][0], fa[i][1], fa[i][2], fa[i][3], ab + aoff[i] + ks);
            #pragma unroll
            for (int jj = 0; jj < 2; jj++)
                ldsm_x4(fb[2 * jj][0], fb[2 * jj][1], fb[2 * jj + 1][0], fb[2 * jj + 1][1],
                        bb + boff[jj] + ks);
            #pragma unroll
            for (int i = 0; i < 2; i++) {
                #pragma unroll
                for (int j = 0; j < 4; j++) {
                    asm volatile(
                        "mma.sync.aligned.m16n8k16.row.col.f32.bf16.bf16.f32 "
                        "{%0,%1,%2,%3},{%4,%5,%6,%7},{%8,%9},{%0,%1,%2,%3};"
                        : "+f"(acc[i][j][0]), "+f"(acc[i][j][1]),
                          "+f"(acc[i][j][2]), "+f"(acc[i][j][3])
                        : "r"(fa[i][0]), "r"(fa[i][1]), "r"(fa[i][2]), "r"(fa[i][3]),
                          "r"(fb[j][0]), "r"(fb[j][1]));
                }
            }
        }
    }

    // Epilogue: dequant + bf16 round + bf16 bias add -> f32
    #pragma unroll
    for (int i = 0; i < 2; i++) {
        int r0 = m0 + wm + i * 16 + g;
        float sx0 = g_xs[r0];
        float sx1 = g_xs[r0 + 8];
        #pragma unroll
        for (int j = 0; j < 4; j++) {
            int c0 = n0 + wn + j * 8 + 2 * tig;
            float sw0 = g_ws[c0], sw1 = g_ws[c0 + 1];
            float bb0 = __bfloat162float(__float2bfloat16(bias[c0]));
            float bb1 = __bfloat162float(__float2bfloat16(bias[c0 + 1]));
            float2 o0, o1;
            o0.x = finish_elem(acc[i][j][0], sx0, sw0, bb0);
            o0.y = finish_elem(acc[i][j][1], sx0, sw1, bb1);
            o1.x = finish_elem(acc[i][j][2], sx1, sw0, bb0);
            o1.y = finish_elem(acc[i][j][3], sx1, sw1, bb1);
            *reinterpret_cast<float2*>(out + (size_t)r0 * N + c0) = o0;
            *reinterpret_cast<float2*>(out + (size_t)(r0 + 8) * N + c0) = o1;
        }
    }
}

// ---------------------------------------------------------------------------
extern "C" void kernel_launch(void* const* d_in, const int* in_sizes, int n_in,
                              void* d_out, int out_size) {
    const float* x      = (const float*)d_in[0];
    const float* weight = (const float*)d_in[1];
    const float* bias   = (const float*)d_in[2];
    float* out = (float*)d_out;

    const int N = in_sizes[2];
    const int K = in_sizes[1] / N;
    const int M = in_sizes[0] / K;

    __nv_bfloat16* wbf; cudaGetSymbolAddress((void**)&wbf, g_wbf);
    __nv_bfloat16* xbf; cudaGetSymbolAddress((void**)&xbf, g_xbf);
    float* ws;          cudaGetSymbolAddress((void**)&ws, g_ws);
    float* xs;          cudaGetSymbolAddress((void**)&xs, g_xs);

    quant_fused_kernel<<<N + M, 256, K * sizeof(float)>>>(weight, x, wbf, xbf, ws, xs, K, N);

    cudaFuncSetAttribute(gemm_bf16_kernel, cudaFuncAttributeMaxDynamicSharedMemorySize, SMEM_BYTES);
    dim3 grid(N / BN, M / BM);
    gemm_bf16_kernel<<<grid, 512, SMEM_BYTES>>>(bias, out, M, N, K);
}

// round 12
// speedup vs baseline: 1.8784x; 1.0020x over previous
#include <cuda_runtime.h>
#include <cuda_bf16.h>
#include <cstdint>

// x [2,4096,4096] f32, weight [4096,4096] f32, bias [4096] f32 -> out f32
// M=8192, K=4096, N=4096
// Quantized operands stored as bf16 (exact for ints in [-128,127]) so the
// GEMM can use mma.sync.m16n8k16.bf16 (fp32 acc) instead of the
// heavily-deprioritized legacy int8 IMMA path on sm_103a.

#define MAX_M 8192
#define MAX_K 4096
#define MAX_N 4096

__device__ __nv_bfloat16 g_xbf[(size_t)MAX_M * MAX_K];
__device__ __nv_bfloat16 g_wbf[(size_t)MAX_N * MAX_K];
__device__ float g_xs[MAX_M];
__device__ float g_ws[MAX_N];

// ---------------------------------------------------------------------------
// Fused per-row symmetric int8 quantization -> bf16-carried int values.
// ---------------------------------------------------------------------------
__global__ void quant_fused_kernel(const float* __restrict__ w,
                                   const float* __restrict__ x,
                                   __nv_bfloat16* __restrict__ wbf,
                                   __nv_bfloat16* __restrict__ xbf,
                                   float* __restrict__ wsc,
                                   float* __restrict__ xsc,
                                   int K, int N) {
    extern __shared__ float4 buf[];  // K floats
    const int b = blockIdx.x;
    const float* src;
    __nv_bfloat16* dst;
    float* sc;
    int row;
    if (b < N) { src = w; dst = wbf; sc = wsc; row = b; }
    else       { src = x; dst = xbf; sc = xsc; row = b - N; }

    const int nk4 = K >> 2;
    const float4* s4 = reinterpret_cast<const float4*>(src) + (size_t)row * nk4;
    __nv_bfloat162* d2 = reinterpret_cast<__nv_bfloat162*>(dst) + (size_t)row * (K >> 1);

    float amax = 0.f;
    for (int i = threadIdx.x; i < nk4; i += blockDim.x) {
        float4 v = s4[i];
        buf[i] = v;
        amax = fmaxf(amax, fmaxf(fmaxf(fabsf(v.x), fabsf(v.y)),
                                 fmaxf(fabsf(v.z), fabsf(v.w))));
    }
    __shared__ float red[32];
    #pragma unroll
    for (int o = 16; o; o >>= 1) amax = fmaxf(amax, __shfl_xor_sync(0xffffffffu, amax, o));
    if ((threadIdx.x & 31) == 0) red[threadIdx.x >> 5] = amax;
    __syncthreads();
    if (threadIdx.x < 32) {
        float v = (threadIdx.x < (blockDim.x >> 5)) ? red[threadIdx.x] : 0.f;
        #pragma unroll
        for (int o = 16; o; o >>= 1) v = fmaxf(v, __shfl_xor_sync(0xffffffffu, v, o));
        if (threadIdx.x == 0) red[0] = fmaxf(v / 127.0f, 1e-12f);
    }
    __syncthreads();
    const float scale = red[0];
    if (threadIdx.x == 0) sc[row] = scale;

    for (int i = threadIdx.x; i < nk4; i += blockDim.x) {
        float4 v = buf[i];
        float q0 = fminf(fmaxf(rintf(v.x / scale), -128.f), 127.f);
        float q1 = fminf(fmaxf(rintf(v.y / scale), -128.f), 127.f);
        float q2 = fminf(fmaxf(rintf(v.z / scale), -128.f), 127.f);
        float q3 = fminf(fmaxf(rintf(v.w / scale), -128.f), 127.f);
        __nv_bfloat162 p0, p1;
        p0.x = __float2bfloat16(q0); p0.y = __float2bfloat16(q1);
        p1.x = __float2bfloat16(q2); p1.y = __float2bfloat16(q3);
        d2[i * 2]     = p0;
        d2[i * 2 + 1] = p1;
    }
}

// ---------------------------------------------------------------------------
// bf16 GEMM: mma.sync.m16n8k16.bf16 + cp.async 5-stage pipeline + ldmatrix.
// Block 128x128, 64B k-slab per stage row (k=32 elems), 16 warps, warp 32x32.
// Byte layout identical to the previous int8 kernel.
// ---------------------------------------------------------------------------
#define BM 128
#define BN 128
#define BKB 64                           // bytes of K per stage row
#define STAGES 5
#define ASTRIDE 80                       // 64B data + 16B pad: conflict-free
#define STAGE_BYTES (2 * BM * ASTRIDE)   // 20480
#define SMEM_BYTES (STAGES * STAGE_BYTES)

__device__ __forceinline__ uint32_t smem_u32(const void* p) {
    uint32_t a;
    asm("{ .reg .u64 t; cvta.to.shared.u64 t, %1; cvt.u32.u64 %0, t; }" : "=r"(a) : "l"(p));
    return a;
}
__device__ __forceinline__ void cp_async16(uint32_t dst, const void* src) {
    asm volatile("cp.async.cg.shared.global [%0], [%1], 16;" :: "r"(dst), "l"(src));
}
__device__ __forceinline__ void cp_commit() {
    asm volatile("cp.async.commit_group;" ::: "memory");
}
template <int W>
__device__ __forceinline__ void cp_wait() {
    asm volatile("cp.async.wait_group %0;" :: "n"(W) : "memory");
}
__device__ __forceinline__ void ldsm_x4(int& r0, int& r1, int& r2, int& r3, uint32_t a) {
    asm volatile("ldmatrix.sync.aligned.m8n8.x4.shared.b16 {%0,%1,%2,%3}, [%4];"
                 : "=r"(r0), "=r"(r1), "=r"(r2), "=r"(r3) : "r"(a));
}

__device__ __forceinline__ float finish_elem(float accf, float sx, float sw, float bias_bf) {
    float v = (rintf(accf) * sx) * sw;                 // acc is integer-valued
    float o = __bfloat162float(__float2bfloat16(v));   // .astype(bf16)
    return __bfloat162float(__float2bfloat16(o + bias_bf));
}

__global__ void __launch_bounds__(512, 1) gemm_bf16_kernel(
    const float* __restrict__ bias, float* __restrict__ out,
    int M, int N, int K) {
    extern __shared__ char smem[];
    const uint32_t sb = smem_u32(smem);

    const int tid = threadIdx.x;
    const int warp = tid >> 5, lane = tid & 31;
    const int m0 = blockIdx.y * BM;
    const int n0 = blockIdx.x * BN;
    const int wm = (warp >> 2) * 32;   // 4 warps in M
    const int wn = (warp & 3) * 32;    // 4 warps in N
    const int g = lane >> 2, tig = lane & 3;

    const int Kb = K * 2;              // row length in bytes
    const int8_t* Ag = reinterpret_cast<const int8_t*>(g_xbf) + (size_t)m0 * Kb;
    const int8_t* Bg = reinterpret_cast<const int8_t*>(g_wbf) + (size_t)n0 * Kb;

    // cp.async: 512 16B segments per tile; 1 A-seg + 1 B-seg per thread.
    const int r_ld = tid >> 2, c_ld = (tid & 3) * 16;

    // ldmatrix lane offsets (byte offsets inside a stage tile)
    uint32_t aoff[2], boff[2];
    #pragma unroll
    for (int i = 0; i < 2; i++)
        aoff[i] = (uint32_t)((wm + i * 16 + (lane & 15)) * ASTRIDE + ((lane >> 4) << 4));
    #pragma unroll
    for (int jj = 0; jj < 2; jj++)
        boff[jj] = (uint32_t)((wn + ((jj << 1) + ((lane >> 4) & 1)) * 8 + (lane & 7)) * ASTRIDE
                              + (((lane >> 3) & 1) << 4));

    float acc[2][4][4];
    #pragma unroll
    for (int i = 0; i < 2; i++)
        #pragma unroll
        for (int j = 0; j < 4; j++)
            #pragma unroll
            for (int r = 0; r < 4; r++) acc[i][j][r] = 0.f;

    const int nchunks = Kb / BKB;      // 128

    auto issue_stage = [&](int c) {
        const int s = c % STAGES;
        const int kt = c * BKB;
        const uint32_t ab = sb + s * STAGE_BYTES;
        const uint32_t bb = ab + BM * ASTRIDE;
        cp_async16(ab + r_ld * ASTRIDE + c_ld, Ag + (size_t)r_ld * Kb + kt + c_ld);
        cp_async16(bb + r_ld * ASTRIDE + c_ld, Bg + (size_t)r_ld * Kb + kt + c_ld);
        cp_commit();
    };

    #pragma unroll
    for (int c = 0; c < STAGES - 1; c++) issue_stage(c);

    for (int c = 0; c < nchunks; c++) {
        cp_wait<STAGES - 2>();
        __syncthreads();

        if (c + STAGES - 1 < nchunks) issue_stage(c + STAGES - 1);
        else cp_commit();   // exactly one commit per iteration

        const int s = c % STAGES;
        const uint32_t ab = sb + s * STAGE_BYTES;
        const uint32_t bb = ab + BM * ASTRIDE;

        #pragma unroll
        for (int ks = 0; ks < BKB; ks += 32) {   // 32B = k16 of bf16
            int fa[2][4], fb[4][2];
            #pragma unroll
            for (int i = 0; i < 2; i++)
                ldsm_x4(fa[i][0], fa[i][1], fa[i][2], fa[i][3], ab + aoff[i] + ks);
            #pragma unroll
            for (int jj = 0; jj < 2; jj++)
                ldsm_x4(fb[2 * jj][0], fb[2 * jj][1], fb[2 * jj + 1][0], fb[2 * jj + 1][1],
                        bb + boff[jj] + ks);
            #pragma unroll
            for (int i = 0; i < 2; i++) {
                #pragma unroll
                for (int j = 0; j < 4; j++) {
                    asm volatile(
                        "mma.sync.aligned.m16n8k16.row.col.f32.bf16.bf16.f32 "
                        "{%0,%1,%2,%3},{%4,%5,%6,%7},{%8,%9},{%0,%1,%2,%3};"
                        : "+f"(acc[i][j][0]), "+f"(acc[i][j][1]),
                          "+f"(acc[i][j][2]), "+f"(acc[i][j][3])
                        : "r"(fa[i][0]), "r"(fa[i][1]), "r"(fa[i][2]), "r"(fa[i][3]),
                          "r"(fb[j][0]), "r"(fb[j][1]));
                }
            }
        }
    }

    // Epilogue: dequant + bf16 round + bf16 bias add -> f32
    #pragma unroll
    for (int i = 0; i < 2; i++) {
        int r0 = m0 + wm + i * 16 + g;
        float sx0 = g_xs[r0];
        float sx1 = g_xs[r0 + 8];
        #pragma unroll
        for (int j = 0; j < 4; j++) {
            int c0 = n0 + wn + j * 8 + 2 * tig;
            float sw0 = g_ws[c0], sw1 = g_ws[c0 + 1];
            float bb0 = __bfloat162float(__float2bfloat16(bias[c0]));
            float bb1 = __bfloat162float(__float2bfloat16(bias[c0 + 1]));
            float2 o0, o1;
            o0.x = finish_elem(acc[i][j][0], sx0, sw0, bb0);
            o0.y = finish_elem(acc[i][j][1], sx0, sw1, bb1);
            o1.x = finish_elem(acc[i][j][2], sx1, sw0, bb0);
            o1.y = finish_elem(acc[i][j][3], sx1, sw1, bb1);
            *reinterpret_cast<float2*>(out + (size_t)r0 * N + c0) = o0;
            *reinterpret_cast<float2*>(out + (size_t)(r0 + 8) * N + c0) = o1;
        }
    }
}

// ---------------------------------------------------------------------------
extern "C" void kernel_launch(void* const* d_in, const int* in_sizes, int n_in,
                              void* d_out, int out_size) {
    const float* x      = (const float*)d_in[0];
    const float* weight = (const float*)d_in[1];
    const float* bias   = (const float*)d_in[2];
    float* out = (float*)d_out;

    const int N = in_sizes[2];
    const int K = in_sizes[1] / N;
    const int M = in_sizes[0] / K;

    __nv_bfloat16* wbf; cudaGetSymbolAddress((void**)&wbf, g_wbf);
    __nv_bfloat16* xbf; cudaGetSymbolAddress((void**)&xbf, g_xbf);
    float* ws;          cudaGetSymbolAddress((void**)&ws, g_ws);
    float* xs;          cudaGetSymbolAddress((void**)&xs, g_xs);

    quant_fused_kernel<<<N + M, 256, K * sizeof(float)>>>(weight, x, wbf, xbf, ws, xs, K, N);

    cudaFuncSetAttribute(gemm_bf16_kernel, cudaFuncAttributeMaxDynamicSharedMemorySize, SMEM_BYTES);
    dim3 grid(N / BN, M / BM);
    gemm_bf16_kernel<<<grid, 512, SMEM_BYTES>>>(bias, out, M, N, K);
}